// round 5
// baseline (speedup 1.0000x reference)
#include <cuda_runtime.h>
#include <math.h>

// Problem constants
#define N        10000
#define DF       32
#define ITERS    4
#define NPAD     10240         // padded j slots (multiple of 32)
#define NCHUNK   320           // 32 j per chunk
#define JSPLIT   32            // j-range splits
#define CPS      10            // chunks per split
#define SPAIRS   160           // packed pairs per split
#define ITILE    128
#define NITILE   80            // 80*32 = 2560 blocks
#define ZSCALE   16384.0f
#define SENTC    50.0f         // sentinel coordinate (never within any band)

// Scratch (static device arrays; cudaMalloc is forbidden)
__device__ float  g_pairs[(NPAD / 2) * 16];   // dual-layout records, sorted slot order
__device__ float4 g_cmeta[NCHUNK];            // per-chunk bbox: center + radius
__device__ int    g_perm[N];                  // sorted slot -> original index
__device__ float  g_xyz[N * 3];               // current positions, ORIGINAL order
__device__ int    g_binbase[4096];
__device__ int    g_bincnt[4096];
__device__ float  g_part[JSPLIT * NPAD * 12]; // partial sums per split
__device__ float  g_h[ITERS * N * DF];
__device__ float  g_stats[ITERS * DF * 2];
__device__ float  g_w[ITERS * N * 3];

// ---------------------------------------------------------------------------
// Morton key: 16^3 grid, cell size 2.0, domain [-16,16)
// ---------------------------------------------------------------------------
__device__ __forceinline__ int spread4(int v) {
    v &= 15;
    v = (v | (v << 4)) & 0x0C3;
    v = (v | (v << 2)) & 0x249;
    return v;
}
__device__ __forceinline__ int cellkey(float x, float y, float z) {
    int cx = min(max((int)((x + 16.f) * 0.5f), 0), 15);
    int cy = min(max((int)((y + 16.f) * 0.5f), 0), 15);
    int cz = min(max((int)((z + 16.f) * 0.5f), 0), 15);
    return spread4(cx) | (spread4(cy) << 1) | (spread4(cz) << 2);
}

// One-block histogram + exclusive scan over 4096 bins.
__global__ void histscan_kernel(const float* __restrict__ X) {
    __shared__ int hist[4096];
    __shared__ int aux[1024];
    int tid = threadIdx.x;
    for (int k = tid; k < 4096; k += 1024) hist[k] = 0;
    __syncthreads();
    for (int i = tid; i < N; i += 1024)
        atomicAdd(&hist[cellkey(X[3*i], X[3*i+1], X[3*i+2])], 1);
    __syncthreads();
    int t = tid * 4;
    int h0 = hist[t], h1 = hist[t+1], h2 = hist[t+2], h3 = hist[t+3];
    int local = h0 + h1 + h2 + h3;
    aux[tid] = local;
    __syncthreads();
    for (int off = 1; off < 1024; off <<= 1) {
        int v = (tid >= off) ? aux[tid - off] : 0;
        __syncthreads();
        aux[tid] += v;
        __syncthreads();
    }
    int base = aux[tid] - local;   // exclusive
    g_binbase[t]     = base;
    g_binbase[t + 1] = base + h0;
    g_binbase[t + 2] = base + h0 + h1;
    g_binbase[t + 3] = base + h0 + h1 + h2;
    g_bincnt[t] = 0; g_bincnt[t+1] = 0; g_bincnt[t+2] = 0; g_bincnt[t+3] = 0;
}

__global__ void scatter_kernel(const float* __restrict__ X) {
    int t = blockIdx.x * blockDim.x + threadIdx.x;
    if (t >= N) return;
    float x = X[3*t], y = X[3*t+1], z = X[3*t+2];
    int key = cellkey(x, y, z);
    int slot = g_binbase[key] + atomicAdd(&g_bincnt[key], 1);
    g_perm[slot] = t;
    g_xyz[3*t] = x; g_xyz[3*t+1] = y; g_xyz[3*t+2] = z;
}

// ---------------------------------------------------------------------------
// Pair record (16 words per packed j-pair):
//   [0..7]  x0 x1 y0 y1 z0 z1 nu0 nu1   (nu = -0.5|x|^2)
//   [8..11] x0 y0 x1 y1                  (packed xy addends)
//   [12,13] round(z*2^14) s32
// ---------------------------------------------------------------------------
__device__ __forceinline__ void write_point_to_pairs(int s, float x, float y, float z) {
    int p = s >> 1, h = s & 1;
    float nu = -0.5f * (x * x + y * y + z * z);
    float* rec = g_pairs + p * 16;
    rec[0 + h] = x;
    rec[2 + h] = y;
    rec[4 + h] = z;
    rec[6 + h] = nu;
    rec[8 + 2 * h] = x;
    rec[9 + 2 * h] = y;
    ((int*)rec)[12 + h] = __float2int_rn(z * ZSCALE);
}

// Build sorted pair records + per-chunk bbox meta (warp == chunk).
__global__ void prep_kernel() {
    int s = blockIdx.x * blockDim.x + threadIdx.x;   // sorted slot, 40x256 = NPAD
    float x = SENTC, y = SENTC, z = SENTC;
    if (s < N) {
        int o = g_perm[s];
        x = g_xyz[3*o]; y = g_xyz[3*o+1]; z = g_xyz[3*o+2];
    }
    write_point_to_pairs(s, x, y, z);
    // warp bbox -> chunk meta
    float mnx = x, mxx = x, mny = y, mxy = y, mnz = z, mxz = z;
    #pragma unroll
    for (int off = 16; off >= 1; off >>= 1) {
        mnx = fminf(mnx, __shfl_xor_sync(0xFFFFFFFF, mnx, off));
        mxx = fmaxf(mxx, __shfl_xor_sync(0xFFFFFFFF, mxx, off));
        mny = fminf(mny, __shfl_xor_sync(0xFFFFFFFF, mny, off));
        mxy = fmaxf(mxy, __shfl_xor_sync(0xFFFFFFFF, mxy, off));
        mnz = fminf(mnz, __shfl_xor_sync(0xFFFFFFFF, mnz, off));
        mxz = fmaxf(mxz, __shfl_xor_sync(0xFFFFFFFF, mxz, off));
    }
    if ((threadIdx.x & 31) == 0) {
        float dx = mxx - mnx, dy = mxy - mny, dz = mxz - mnz;
        g_cmeta[s >> 5] = make_float4(0.5f * (mnx + mxx), 0.5f * (mny + mxy),
                                      0.5f * (mnz + mxz),
                                      0.5f * sqrtf(dx*dx + dy*dy + dz*dz));
    }
}

// ---------------------------------------------------------------------------
// Logits pipeline (unchanged)
// ---------------------------------------------------------------------------
__global__ void linear1_kernel(const float* __restrict__ Xfea,
                               const float* __restrict__ W1,
                               const float* __restrict__ b1) {
    int it = blockIdx.y;
    int n  = blockIdx.x * blockDim.x + threadIdx.x;
    __shared__ float sW[DF * DF];
    __shared__ float sb[DF];
    for (int k = threadIdx.x; k < DF * DF; k += blockDim.x) sW[k] = W1[it * DF * DF + k];
    if (threadIdx.x < DF) sb[threadIdx.x] = b1[it * DF + threadIdx.x];
    __syncthreads();
    if (n >= N) return;
    float xf[DF];
    const float4* xr = (const float4*)(Xfea + n * DF);
    #pragma unroll
    for (int q = 0; q < DF / 4; q++) {
        float4 v = xr[q];
        xf[4*q] = v.x; xf[4*q+1] = v.y; xf[4*q+2] = v.z; xf[4*q+3] = v.w;
    }
    float* hout = g_h + (it * N + n) * DF;
    #pragma unroll 4
    for (int f = 0; f < DF; f++) {
        float acc = sb[f];
        #pragma unroll
        for (int k = 0; k < DF; k++) acc = fmaf(xf[k], sW[f * DF + k], acc);
        hout[f] = acc;
    }
}

__global__ void bnstats_kernel() {
    int it = blockIdx.x;
    int w  = threadIdx.x >> 5;
    int f  = threadIdx.x & 31;
    float s = 0.f, sq = 0.f;
    for (int n = w; n < N; n += 32) {
        float v = g_h[(it * N + n) * DF + f];
        s += v;
        sq = fmaf(v, v, sq);
    }
    __shared__ float ss[32 * 33];
    __shared__ float sqq[32 * 33];
    ss [w * 33 + f] = s;
    sqq[w * 33 + f] = sq;
    __syncthreads();
    if (threadIdx.x < DF) {
        float ts = 0.f, tq = 0.f;
        for (int ww = 0; ww < 32; ww++) { ts += ss[ww * 33 + f]; tq += sqq[ww * 33 + f]; }
        float mu  = ts / (float)N;
        float var = tq / (float)N - mu * mu;
        g_stats[(it * DF + f) * 2 + 0] = mu;
        g_stats[(it * DF + f) * 2 + 1] = rsqrtf(var + 1e-5f);
    }
}

__global__ void logits_kernel(const float* __restrict__ gamma,
                              const float* __restrict__ beta,
                              const float* __restrict__ W2,
                              const float* __restrict__ b2) {
    int it = blockIdx.y;
    int n  = blockIdx.x * blockDim.x + threadIdx.x;
    __shared__ float sg[DF], sbe[DF], smu[DF], sis[DF], sW2[3 * DF], sb2[3];
    if (threadIdx.x < DF) {
        sg [threadIdx.x] = gamma[it * DF + threadIdx.x];
        sbe[threadIdx.x] = beta [it * DF + threadIdx.x];
        smu[threadIdx.x] = g_stats[(it * DF + threadIdx.x) * 2 + 0];
        sis[threadIdx.x] = g_stats[(it * DF + threadIdx.x) * 2 + 1];
    }
    if (threadIdx.x < 3 * DF) sW2[threadIdx.x] = W2[it * 3 * DF + threadIdx.x];
    if (threadIdx.x < 3)      sb2[threadIdx.x] = b2[it * 3 + threadIdx.x];
    __syncthreads();
    if (n >= N) return;
    const float* hrow = g_h + (it * N + n) * DF;
    float a[DF];
    #pragma unroll
    for (int f = 0; f < DF; f++) {
        float v = (hrow[f] - smu[f]) * sis[f] * sg[f] + sbe[f];
        a[f] = fmaxf(v, 0.f);
    }
    float l0 = sb2[0], l1 = sb2[1], l2 = sb2[2];
    #pragma unroll
    for (int f = 0; f < DF; f++) {
        l0 = fmaf(a[f], sW2[0 * DF + f], l0);
        l1 = fmaf(a[f], sW2[1 * DF + f], l1);
        l2 = fmaf(a[f], sW2[2 * DF + f], l2);
    }
    float m = fmaxf(l0, fmaxf(l1, l2));
    float* wout = g_w + (it * N + n) * 3;
    wout[0] = expf(l0 - m);
    wout[1] = expf(l1 - m);
    wout[2] = expf(l2 - m);
}

// ---------------------------------------------------------------------------
// Culled mean-shift pair loop.
// ---------------------------------------------------------------------------
__global__ void __launch_bounds__(ITILE, 9) shift_kernel() {
    __shared__ __align__(16) float  sj[SPAIRS * 16];   // 10.2 KB
    __shared__ float4 smeta[CPS];

    int js  = blockIdx.y;
    int tid = threadIdx.x;

    const float4* src = (const float4*)(g_pairs + js * SPAIRS * 16);
    float4* d4 = (float4*)sj;
    #pragma unroll
    for (int t = tid; t < SPAIRS * 4; t += ITILE) d4[t] = src[t];
    if (tid < CPS) smeta[tid] = g_cmeta[js * CPS + tid];

    int slot = blockIdx.x * ITILE + tid;
    int ii   = (slot < N) ? slot : (N - 1);
    int pb = (ii >> 1) * 16, h = ii & 1;
    float xi  = g_pairs[pb + 0 + h];
    float yi  = g_pairs[pb + 2 + h];
    float zi  = g_pairs[pb + 4 + h];
    float nui = g_pairs[pb + 6 + h];
    float th1 = -nui - 0.02f;    // bw=0.2
    float th2 = -nui - 1.445f;   // bw=1.7
    float th3 = -nui - 5.12f;    // bw=3.2

    // warp bbox over own points
    float mnx = xi, mxx = xi, mny = yi, mxy = yi, mnz = zi, mxz = zi;
    #pragma unroll
    for (int off = 16; off >= 1; off >>= 1) {
        mnx = fminf(mnx, __shfl_xor_sync(0xFFFFFFFF, mnx, off));
        mxx = fmaxf(mxx, __shfl_xor_sync(0xFFFFFFFF, mxx, off));
        mny = fminf(mny, __shfl_xor_sync(0xFFFFFFFF, mny, off));
        mxy = fmaxf(mxy, __shfl_xor_sync(0xFFFFFFFF, mxy, off));
        mnz = fminf(mnz, __shfl_xor_sync(0xFFFFFFFF, mnz, off));
        mxz = fmaxf(mxz, __shfl_xor_sync(0xFFFFFFFF, mxz, off));
    }
    float wcx = 0.5f * (mnx + mxx), wcy = 0.5f * (mny + mxy), wcz = 0.5f * (mnz + mxz);
    float ddx = mxx - mnx, ddy = mxy - mny, ddz = mxz - mnz;
    float wr  = 0.5f * sqrtf(ddx*ddx + ddy*ddy + ddz*ddz);

    __syncthreads();

    // classify chunks (warp-uniform)
    unsigned m_full = 0, m_b3 = 0;
    #pragma unroll
    for (int c = 0; c < CPS; c++) {
        float4 m = smeta[c];
        float dx = wcx - m.x, dy = wcy - m.y, dz = wcz - m.z;
        float d2 = dx*dx + dy*dy + dz*dz;
        float s3 = 3.2f + wr + m.w;
        float s2 = 1.7f + wr + m.w;
        bool any  = d2 <= s3 * s3;
        bool full = d2 <= s2 * s2;
        m_full |= (unsigned)full << c;
        m_b3   |= (unsigned)(any && !full) << c;
    }

    unsigned long long xi2, yi2, zi2;
    asm("mov.b64 %0, {%1, %1};" : "=l"(xi2) : "f"(xi));
    asm("mov.b64 %0, {%1, %1};" : "=l"(yi2) : "f"(yi));
    asm("mov.b64 %0, {%1, %1};" : "=l"(zi2) : "f"(zi));

    unsigned long long axy1 = 0ull, axy2 = 0ull, axy3 = 0ull;
    int   az1 = 0, az2 = 0, az3 = 0;
    int   ac1 = 0, ac2 = 0;
    float fc3 = 0.0f;

    // band3-only chunks
    while (m_b3) {
        int c = __ffs(m_b3) - 1;
        m_b3 &= m_b3 - 1;
        #pragma unroll 4
        for (int p = c * 16; p < c * 16 + 16; p++) {
            const float* rec = sj + p * 16;
            unsigned long long x01  = *(const unsigned long long*)(rec + 0);
            unsigned long long y01  = *(const unsigned long long*)(rec + 2);
            unsigned long long z01  = *(const unsigned long long*)(rec + 4);
            unsigned long long nu01 = *(const unsigned long long*)(rec + 6);
            unsigned long long xy0  = *(const unsigned long long*)(rec + 8);
            unsigned long long xy1  = *(const unsigned long long*)(rec + 10);
            int zf0 = ((const int*)rec)[12];
            int zf1 = ((const int*)rec)[13];
            asm("{\n\t"
                ".reg .b64  t64;\n\t"
                ".reg .f32  vl, vh;\n\t"
                ".reg .pred pl, ph;\n\t"
                "fma.rn.f32x2 t64, %3, %6, %9;\n\t"
                "fma.rn.f32x2 t64, %4, %7, t64;\n\t"
                "fma.rn.f32x2 t64, %5, %8, t64;\n\t"
                "mov.b64 {vl, vh}, t64;\n\t"
                "setp.ge.f32 pl, vl, %10;\n\t"
                "setp.ge.f32 ph, vh, %10;\n\t"
                "@pl add.rn.f32x2 %0, %0, %11;\n\t"
                "@pl add.s32 %1, %1, %13;\n\t"
                "@pl add.f32 %2, %2, 0F3F800000;\n\t"
                "@ph add.rn.f32x2 %0, %0, %12;\n\t"
                "@ph add.s32 %1, %1, %14;\n\t"
                "@ph add.f32 %2, %2, 0F3F800000;\n\t"
                "}"
                : "+l"(axy3), "+r"(az3), "+f"(fc3)
                : "l"(xi2), "l"(yi2), "l"(zi2),
                  "l"(x01), "l"(y01), "l"(z01), "l"(nu01),
                  "f"(th3), "l"(xy0), "l"(xy1), "r"(zf0), "r"(zf1));
        }
    }

    // full 3-band chunks
    while (m_full) {
        int c = __ffs(m_full) - 1;
        m_full &= m_full - 1;
        #pragma unroll 4
        for (int p = c * 16; p < c * 16 + 16; p++) {
            const float* rec = sj + p * 16;
            unsigned long long x01  = *(const unsigned long long*)(rec + 0);
            unsigned long long y01  = *(const unsigned long long*)(rec + 2);
            unsigned long long z01  = *(const unsigned long long*)(rec + 4);
            unsigned long long nu01 = *(const unsigned long long*)(rec + 6);
            unsigned long long xy0  = *(const unsigned long long*)(rec + 8);
            unsigned long long xy1  = *(const unsigned long long*)(rec + 10);
            int zf0 = ((const int*)rec)[12];
            int zf1 = ((const int*)rec)[13];
            asm("{\n\t"
                ".reg .b64  t64;\n\t"
                ".reg .f32  vl, vh;\n\t"
                ".reg .pred pl1, pl2, pl3, ph1, ph2, ph3;\n\t"
                "fma.rn.f32x2 t64, %9, %12, %15;\n\t"
                "fma.rn.f32x2 t64, %10, %13, t64;\n\t"
                "fma.rn.f32x2 t64, %11, %14, t64;\n\t"
                "mov.b64 {vl, vh}, t64;\n\t"
                "setp.ge.f32 pl1, vl, %16;\n\t"
                "setp.ge.f32 pl2, vl, %17;\n\t"
                "setp.ge.f32 pl3, vl, %18;\n\t"
                "setp.ge.f32 ph1, vh, %16;\n\t"
                "setp.ge.f32 ph2, vh, %17;\n\t"
                "setp.ge.f32 ph3, vh, %18;\n\t"
                "@pl1 add.rn.f32x2 %0, %0, %19;\n\t"
                "@pl1 add.s32 %3, %3, %21;\n\t"
                "@pl1 add.s32 %6, %6, 1;\n\t"
                "@pl2 add.rn.f32x2 %1, %1, %19;\n\t"
                "@pl2 add.s32 %4, %4, %21;\n\t"
                "@pl2 add.s32 %7, %7, 1;\n\t"
                "@pl3 add.rn.f32x2 %2, %2, %19;\n\t"
                "@pl3 add.s32 %5, %5, %21;\n\t"
                "@pl3 add.f32 %8, %8, 0F3F800000;\n\t"
                "@ph1 add.rn.f32x2 %0, %0, %20;\n\t"
                "@ph1 add.s32 %3, %3, %22;\n\t"
                "@ph1 add.s32 %6, %6, 1;\n\t"
                "@ph2 add.rn.f32x2 %1, %1, %20;\n\t"
                "@ph2 add.s32 %4, %4, %22;\n\t"
                "@ph2 add.s32 %7, %7, 1;\n\t"
                "@ph3 add.rn.f32x2 %2, %2, %20;\n\t"
                "@ph3 add.s32 %5, %5, %22;\n\t"
                "@ph3 add.f32 %8, %8, 0F3F800000;\n\t"
                "}"
                : "+l"(axy1), "+l"(axy2), "+l"(axy3),
                  "+r"(az1), "+r"(az2), "+r"(az3),
                  "+r"(ac1), "+r"(ac2), "+f"(fc3)
                : "l"(xi2), "l"(yi2), "l"(zi2),
                  "l"(x01), "l"(y01), "l"(z01), "l"(nu01),
                  "f"(th1), "f"(th2), "f"(th3),
                  "l"(xy0), "l"(xy1), "r"(zf0), "r"(zf1));
        }
    }

    float* dst = g_part + (js * NPAD + slot) * 12;
    ((float4*)dst)[0] = make_float4(
        __uint_as_float((unsigned)axy1), __uint_as_float((unsigned)(axy1 >> 32)),
        __uint_as_float((unsigned)axy2), __uint_as_float((unsigned)(axy2 >> 32)));
    ((float4*)dst)[1] = make_float4(
        __uint_as_float((unsigned)axy3), __uint_as_float((unsigned)(axy3 >> 32)),
        __int_as_float(az1), __int_as_float(az2));
    ((float4*)dst)[2] = make_float4(
        __int_as_float(az3), __int_as_float(ac1),
        __int_as_float(ac2), fc3);
}

// Finalize: reduce splits, apply weights, write out[orig] and g_xyz[orig].
__global__ void finalize_kernel(float* __restrict__ out, int it) {
    int s = blockIdx.x * blockDim.x + threadIdx.x;
    if (s >= N) return;
    float sx1=0,sy1=0,sx2=0,sy2=0,sx3=0,sy3=0, c3=0.f;
    int   z1=0,z2=0,z3=0, c1=0,c2=0;
    #pragma unroll 4
    for (int js = 0; js < JSPLIT; js++) {
        const float4* p = (const float4*)(g_part + (js * NPAD + s) * 12);
        float4 v0 = p[0], v1 = p[1], v2 = p[2];
        sx1 += v0.x; sy1 += v0.y; sx2 += v0.z; sy2 += v0.w;
        sx3 += v1.x; sy3 += v1.y;
        z1 += __float_as_int(v1.z); z2 += __float_as_int(v1.w);
        z3 += __float_as_int(v2.x);
        c1 += __float_as_int(v2.y); c2 += __float_as_int(v2.z); c3 += v2.w;
    }
    float sz1 = (float)z1 * (1.0f / ZSCALE);
    float sz2 = (float)z2 * (1.0f / ZSCALE);
    float sz3 = (float)z3 * (1.0f / ZSCALE);
    int o = g_perm[s];
    const float* wp = g_w + (it * N + o) * 3;
    float e0 = wp[0], e1 = wp[1], e2 = wp[2];
    float inv = 1.0f / (e0 + e1 + e2);
    float r1 = e0 / (float)c1, r2 = e1 / (float)c2, r3 = e2 / c3;
    float nx = (sx1 * r1 + sx2 * r2 + sx3 * r3) * inv;
    float ny = (sy1 * r1 + sy2 * r2 + sy3 * r3) * inv;
    float nz = (sz1 * r1 + sz2 * r2 + sz3 * r3) * inv;
    float* oo = out + (it * N + o) * 3;
    oo[0] = nx; oo[1] = ny; oo[2] = nz;
    g_xyz[3*o] = nx; g_xyz[3*o+1] = ny; g_xyz[3*o+2] = nz;
}

// ---------------------------------------------------------------------------
// Inputs: 0:X 1:X_fea 2:W1 3:b1 4:gamma 5:beta 6:W2 7:b2   Output: [4,N,3] f32
// shift_kernel at launch index 3 (ncu capture point).
// ---------------------------------------------------------------------------
extern "C" void kernel_launch(void* const* d_in, const int* in_sizes, int n_in,
                              void* d_out, int out_size) {
    const float* X     = (const float*)d_in[0];
    const float* Xfea  = (const float*)d_in[1];
    const float* W1    = (const float*)d_in[2];
    const float* b1    = (const float*)d_in[3];
    const float* gamma = (const float*)d_in[4];
    const float* beta  = (const float*)d_in[5];
    const float* W2    = (const float*)d_in[6];
    const float* b2    = (const float*)d_in[7];
    float* out = (float*)d_out;

    histscan_kernel<<<1, 1024>>>(X);                                           // 0
    scatter_kernel<<<(N + 255) / 256, 256>>>(X);                               // 1
    prep_kernel<<<NPAD / 256, 256>>>();                                        // 2
    shift_kernel<<<dim3(NITILE, JSPLIT), ITILE>>>();                           // 3 <- ncu
    linear1_kernel<<<dim3((N + 127) / 128, ITERS), 128>>>(Xfea, W1, b1);       // 4
    bnstats_kernel<<<ITERS, 1024>>>();                                         // 5
    logits_kernel<<<dim3((N + 255) / 256, ITERS), 256>>>(gamma, beta, W2, b2); // 6
    finalize_kernel<<<(N + 255) / 256, 256>>>(out, 0);                         // 7
    for (int it = 1; it < ITERS; it++) {
        prep_kernel<<<NPAD / 256, 256>>>();
        shift_kernel<<<dim3(NITILE, JSPLIT), ITILE>>>();
        finalize_kernel<<<(N + 255) / 256, 256>>>(out, it);
    }
}